// round 2
// baseline (speedup 1.0000x reference)
#include <cuda_runtime.h>

#define Bsz 512
#define Tt  128
#define Ff  256
#define Hh  384
#define Ll  3
#define Kw  10
#define LAB 25
#define CHh 128
#define GATES 1542   // 4*H + 2*L

// ---------------- device scratch (static: no allocations allowed) ----------------
__device__ float g_xw[(size_t)Bsz * Tt * GATES];   // [m=b*T+t][GATES]  ~404 MB
__device__ float g_xo[Bsz * GATES];                // per-step gate pre-activations
__device__ float g_h[Bsz * Hh];
__device__ float g_c[Bsz * Hh];
__device__ float g_hhist[(size_t)Tt * Bsz * Hh];   // full h history ~100 MB
__device__ float g_dist[Tt * Bsz];

__device__ __forceinline__ float sigf(float x) { return 1.0f / (1.0f + __expf(-x)); }

// ---------------- init: zero recurrent state ----------------
__global__ void init_state() {
    int i = blockIdx.x * blockDim.x + threadIdx.x;
    if (i < Bsz * Hh) { g_h[i] = 0.0f; g_c[i] = 0.0f; }
}

// ---------------- big GEMM: g_xw = [X, t>0] @ kernel_w + kernel_b ----------------
// M=65536 (m=b*T+t), K=256, N=1542. BM=BN=128, BK=16, 256 thr, 8x8 micro.
__global__ __launch_bounds__(256) void gemm_xw(const float* __restrict__ X,
                                               const float* __restrict__ kw,
                                               const float* __restrict__ kb) {
    __shared__ __align__(16) float As[16][128];
    __shared__ __align__(16) float Bs[16][128];
    const int bn = blockIdx.x * 128, bm = blockIdx.y * 128;
    const int tid = threadIdx.x;
    const int tm = (tid >> 4) << 3, tn = (tid & 15) << 3;
    float acc[8][8];
#pragma unroll
    for (int i = 0; i < 8; i++)
#pragma unroll
        for (int j = 0; j < 8; j++) acc[i][j] = 0.0f;

    for (int k0 = 0; k0 < Ff; k0 += 16) {
#pragma unroll
        for (int r = 0; r < 2; r++) {
            int fi = tid + 256 * r;
            int row = fi >> 2, kq = fi & 3;
            float4 v = *(const float4*)(X + (size_t)(bm + row) * Ff + k0 + kq * 4);
            As[kq * 4 + 0][row] = v.x; As[kq * 4 + 1][row] = v.y;
            As[kq * 4 + 2][row] = v.z; As[kq * 4 + 3][row] = v.w;
        }
#pragma unroll
        for (int r = 0; r < 4; r++) {
            int i2 = tid + 256 * r;
            int k = i2 >> 6, np = (i2 & 63) << 1;
            int n = bn + np;
            float2 v = make_float2(0.0f, 0.0f);
            if (n < GATES) v = *(const float2*)(kw + (size_t)(k0 + k) * GATES + n);
            Bs[k][np] = v.x; Bs[k][np + 1] = v.y;
        }
        __syncthreads();
#pragma unroll
        for (int kk = 0; kk < 16; kk++) {
            float4 a0 = *(const float4*)&As[kk][tm];
            float4 a1 = *(const float4*)&As[kk][tm + 4];
            float4 b0 = *(const float4*)&Bs[kk][tn];
            float4 b1 = *(const float4*)&Bs[kk][tn + 4];
            float av[8] = {a0.x, a0.y, a0.z, a0.w, a1.x, a1.y, a1.z, a1.w};
            float bv[8] = {b0.x, b0.y, b0.z, b0.w, b1.x, b1.y, b1.z, b1.w};
#pragma unroll
            for (int i = 0; i < 8; i++)
#pragma unroll
                for (int j = 0; j < 8; j++) acc[i][j] += av[i] * bv[j];
        }
        __syncthreads();
    }
#pragma unroll
    for (int i = 0; i < 8; i++) {
        int m = bm + tm + i;
        int t = m & (Tt - 1);
#pragma unroll
        for (int j = 0; j < 8; j++) {
            int n = bn + tn + j;
            if (n < GATES) {
                float v = acc[i][j] + kb[n];
                if (t > 0) v += kw[(size_t)Ff * GATES + n];
                g_xw[(size_t)m * GATES + n] = v;
            }
        }
    }
}

// ---------------- per-step GEMM: g_xo = g_xw[:,t] + h @ rec_w + rec_b (+t row) ----
// M=512, K=384, N=1542. BM=BN=64, BK=16, 256 thr, 4x4 micro. Grid (25, 8).
__global__ __launch_bounds__(256) void gemm_rec(const float* __restrict__ rw,
                                                const float* __restrict__ rb,
                                                int t) {
    __shared__ __align__(16) float As[16][64];
    __shared__ __align__(16) float Bs[16][64];
    const int bn = blockIdx.x * 64, bm = blockIdx.y * 64;
    const int tid = threadIdx.x;
    const int tm = (tid >> 4) << 2, tn = (tid & 15) << 2;
    float acc[4][4];
#pragma unroll
    for (int i = 0; i < 4; i++)
#pragma unroll
        for (int j = 0; j < 4; j++) acc[i][j] = 0.0f;

    for (int k0 = 0; k0 < Hh; k0 += 16) {
        {
            int row = tid >> 2, kq = tid & 3;
            float4 v = *(const float4*)(g_h + (size_t)(bm + row) * Hh + k0 + kq * 4);
            As[kq * 4 + 0][row] = v.x; As[kq * 4 + 1][row] = v.y;
            As[kq * 4 + 2][row] = v.z; As[kq * 4 + 3][row] = v.w;
        }
#pragma unroll
        for (int r = 0; r < 2; r++) {
            int i2 = tid + 256 * r;
            int k = i2 >> 5, np = (i2 & 31) << 1;
            int n = bn + np;
            float2 v = make_float2(0.0f, 0.0f);
            if (n < GATES) v = *(const float2*)(rw + (size_t)(k0 + k) * GATES + n);
            Bs[k][np] = v.x; Bs[k][np + 1] = v.y;
        }
        __syncthreads();
#pragma unroll
        for (int kk = 0; kk < 16; kk++) {
            float4 a = *(const float4*)&As[kk][tm];
            float4 bv = *(const float4*)&Bs[kk][tn];
            float av[4] = {a.x, a.y, a.z, a.w};
            float bw[4] = {bv.x, bv.y, bv.z, bv.w};
#pragma unroll
            for (int i = 0; i < 4; i++)
#pragma unroll
                for (int j = 0; j < 4; j++) acc[i][j] += av[i] * bw[j];
        }
        __syncthreads();
    }
#pragma unroll
    for (int i = 0; i < 4; i++) {
        int row = bm + tm + i;
#pragma unroll
        for (int j = 0; j < 4; j++) {
            int n = bn + tn + j;
            if (n < GATES) {
                float v = acc[i][j] + g_xw[((size_t)row * Tt + t) * GATES + n] + rb[n];
                if (t > 0) v += rw[(size_t)Hh * GATES + n];
                g_xo[row * GATES + n] = v;
            }
        }
    }
}

// ---------------- gates + state update; 512 blocks x 384 threads ----------------
__global__ void step_update(int t) {
    const int b = blockIdx.x;
    const int h = threadIdx.x;
    __shared__ float s_fm[Ll], s_im[Ll];
    const float* xo = g_xo + (size_t)b * GATES;

    if (h == 0) {
        float a0 = xo[0], a1 = xo[1], a2 = xo[2];
        float m = fmaxf(a0, fmaxf(a1, a2));
        float e0 = __expf(a0 - m), e1 = __expf(a1 - m), e2 = __expf(a2 - m);
        float inv = 1.0f / (e0 + e1 + e2);
        float f0 = e0 * inv, f1 = (e0 + e1) * inv, f2 = (e0 + e1 + e2) * inv;
        s_fm[0] = f0; s_fm[1] = f1; s_fm[2] = f2;
        float b0 = xo[3], b1 = xo[4], b2 = xo[5];
        float m2 = fmaxf(b0, fmaxf(b1, b2));
        float g0 = __expf(b0 - m2), g1 = __expf(b1 - m2), g2 = __expf(b2 - m2);
        float inv2 = 1.0f / (g0 + g1 + g2);
        s_im[2] = g2 * inv2; s_im[1] = (g1 + g2) * inv2; s_im[0] = (g0 + g1 + g2) * inv2;
        g_dist[t * Bsz + b] = 1.0f - (f0 + f1 + f2) * (1.0f / 3.0f);
    }
    __syncthreads();

    const int l = h >> 7, ch = h & 127;
    float gf  = xo[6 + l * CHh + ch];
    float gi  = xo[6 + (Ll + l) * CHh + ch];
    float go  = xo[6 + (2 * Ll + l) * CHh + ch];
    float gci = xo[6 + (3 * Ll + l) * CHh + ch];
    float f = sigf(gf), iG = sigf(gi), o = sigf(go), cin = tanhf(gci);
    float c = g_c[(size_t)b * Hh + h];
    float F = s_fm[l], I = s_im[l], ov = F * I;
    float cn = ov * (f * c + iG * cin) + (F - ov) * c + (I - ov) * cin;
    g_c[(size_t)b * Hh + h] = cn;
    float hn = o * tanhf(cn);
    g_h[(size_t)b * Hh + h] = hn;
    g_hhist[((size_t)t * Bsz + b) * Hh + h] = hn;
}

// ---------------- finalize: per-batch theme/conv/out at t = v_len-1 ----------------
// GROUP=4 batches per block to reuse conv_w reads. 128 blocks x 384 threads.
#define GROUP 4
#define FIN_SMEM_FLOATS (GROUP * 3840 + GROUP * Hh + GROUP * Hh + GROUP * 64 + GROUP * Kw + GROUP * Kw + GROUP)
__global__ __launch_bounds__(384) void finalize(
    const int* __restrict__ vlen,
    const float* __restrict__ sw, const float* __restrict__ sb,
    const float* __restrict__ rsw, const float* __restrict__ rsb,
    const float* __restrict__ cw, const float* __restrict__ cb,
    const float* __restrict__ ow, const float* __restrict__ ob,
    float* __restrict__ out) {
    extern __shared__ float sm[];
    float* lh   = sm;                      // GROUP * (Kw*Hh)
    float* th   = lh + GROUP * 3840;       // GROUP * Hh
    float* rn   = th + GROUP * Hh;         // GROUP * Hh
    float* s1   = rn + GROUP * Hh;         // GROUP * 64
    float* ldw  = s1 + GROUP * 64;         // GROUP * Kw
    float* dtmp = ldw + GROUP * Kw;        // GROUP * Kw
    int*   tbs  = (int*)(dtmp + GROUP * Kw);

    const int tid = threadIdx.x;
    const int b0 = blockIdx.x * GROUP;

    if (tid < GROUP) tbs[tid] = vlen[b0 + tid] - 1;
    __syncthreads();
    if (tid < GROUP * Kw) {
        int g = tid / Kw, j = tid % Kw;
        int ts = tbs[g] - (Kw - 1) + j;
        dtmp[g * Kw + j] = (ts >= 0) ? g_dist[ts * Bsz + b0 + g] : 0.0f;
    }
    __syncthreads();
    if (tid < GROUP) {
        float c = 0.0f, cums[Kw];
#pragma unroll
        for (int j = 0; j < Kw; j++) { c += dtmp[tid * Kw + j]; cums[j] = c; }
        float m = cums[Kw - 1];  // dist >= 0 so cumsum is nondecreasing
        float s = 0.0f, e[Kw];
#pragma unroll
        for (int j = 0; j < Kw; j++) { e[j] = __expf(cums[j] - m); s += e[j]; }
        float inv = 1.0f / s;
#pragma unroll
        for (int j = 0; j < Kw; j++) ldw[tid * Kw + j] = e[j] * inv;
    }
    __syncthreads();

    // local_h and theme-raw (mean over window)
    for (int g = 0; g < GROUP; g++) {
        int tb = tbs[g], b = b0 + g;
        float tr = 0.0f;
#pragma unroll
        for (int j = 0; j < Kw; j++) {
            int ts = tb - (Kw - 1) + j;
            float hv = (ts >= 0) ? g_hhist[((size_t)ts * Bsz + b) * Hh + tid] : 0.0f;
            float v = hv * ldw[g * Kw + j];
            lh[g * 3840 + j * Hh + tid] = v;
            tr += v;
        }
        th[g * Hh + tid] = tr * 0.1f;
    }
    __syncthreads();

    // s1 = relu(theme @ scale_w + scale_b)  — 256 threads: (g, j)
    if (tid < GROUP * 64) {
        int g = tid >> 6, j = tid & 63;
        float a = sb[j];
        for (int h = 0; h < Hh; h++) a += th[g * Hh + h] * sw[h * 64 + j];
        s1[g * 64 + j] = fmaxf(a, 0.0f);
    }
    __syncthreads();

    // conv[o] for GROUP batches, reusing each conv_w element 4x
    float accv[GROUP];
    float cbv = cb[tid];
#pragma unroll
    for (int g = 0; g < GROUP; g++) accv[g] = cbv;
    const float2* cwp = (const float2*)(cw + (size_t)tid * (Hh * Kw));
    for (int h = 0; h < Hh; h++) {
#pragma unroll
        for (int jp = 0; jp < Kw / 2; jp++) {
            float2 w = cwp[h * (Kw / 2) + jp];
            int j0 = jp * 2;
#pragma unroll
            for (int g = 0; g < GROUP; g++) {
                accv[g] += lh[g * 3840 + j0 * Hh + h] * w.x
                         + lh[g * 3840 + (j0 + 1) * Hh + h] * w.y;
            }
        }
    }

    // theme2 = sigmoid(s1 @ rescale_w + rescale_b); rnn = h_final + theme2*conv
    for (int g = 0; g < GROUP; g++) {
        float a = rsb[tid];
#pragma unroll
        for (int j = 0; j < 64; j++) a += s1[g * 64 + j] * rsw[j * Hh + tid];
        float t2 = sigf(a);
        int tb = tbs[g], b = b0 + g;
        float hf = g_hhist[((size_t)tb * Bsz + b) * Hh + tid];
        rn[g * Hh + tid] = hf + t2 * accv[g];
    }
    __syncthreads();

    // out = rnn @ out_w + out_b ; write selected timestep output
    if (tid < GROUP * LAB) {
        int g = tid / LAB, lab = tid % LAB;
        float a = ob[lab];
        for (int h = 0; h < Hh; h++) a += rn[g * Hh + h] * ow[h * LAB + lab];
        out[(b0 + g) * LAB + lab] = a;
    }
}

// ---------------- launch ----------------
extern "C" void kernel_launch(void* const* d_in, const int* in_sizes, int n_in,
                              void* d_out, int out_size) {
    const float* X   = (const float*)d_in[0];
    const int*   vlen= (const int*)  d_in[1];
    const float* kw  = (const float*)d_in[2];
    const float* kb  = (const float*)d_in[3];
    const float* rw  = (const float*)d_in[4];
    const float* rb  = (const float*)d_in[5];
    const float* sw  = (const float*)d_in[6];
    const float* sb  = (const float*)d_in[7];
    const float* rsw = (const float*)d_in[8];
    const float* rsb = (const float*)d_in[9];
    const float* cw  = (const float*)d_in[10];
    const float* cb  = (const float*)d_in[11];
    const float* ow  = (const float*)d_in[12];
    const float* ob  = (const float*)d_in[13];
    float* out = (float*)d_out;

    cudaFuncSetAttribute(finalize, cudaFuncAttributeMaxDynamicSharedMemorySize,
                         FIN_SMEM_FLOATS * (int)sizeof(float));

    init_state<<<(Bsz * Hh + 511) / 512, 512>>>();
    gemm_xw<<<dim3((GATES + 127) / 128, (Bsz * Tt) / 128), 256>>>(X, kw, kb);
    for (int t = 0; t < Tt; t++) {
        gemm_rec<<<dim3((GATES + 63) / 64, Bsz / 64), 256>>>(rw, rb, t);
        step_update<<<Bsz, Hh>>>(t);
    }
    finalize<<<Bsz / GROUP, Hh, FIN_SMEM_FLOATS * (int)sizeof(float)>>>(
        vlen, sw, sb, rsw, rsb, cw, cb, ow, ob, out);
}